// round 3
// baseline (speedup 1.0000x reference)
#include <cuda_runtime.h>

// A is [16384, 512] fp32 row-major.
// out = (||colsum||^2 - sum(A*A)) / (n*(n-1))
#define D      512
#define D4     128                  // float4 chunks per row
#define GRID   1024
#define TPB    512
#define ROWS_PER_BLOCK 16           // 4 phases x 4 rows
#define FAST_ROWS 16384             // GRID * ROWS_PER_BLOCK

// Persistent scratch (no allocs allowed). Zero at load; last block re-zeroes
// after producing the output so every graph replay sees clean state.
__device__ float        g_colsum[D];
__device__ float        g_sumsq;
__device__ unsigned int g_count;

__global__ void __launch_bounds__(TPB, 2)
ddc2_fused_kernel(const float* __restrict__ A, int n_rows, float* __restrict__ out) {
    const int t  = threadIdx.x;
    const int c4 = t & (D4 - 1);     // float4 column chunk owned by this thread
    const int rs = t >> 7;           // row phase 0..3 within the block

    const float4* __restrict__ A4 = reinterpret_cast<const float4*>(A);

    float ax = 0.f, ay = 0.f, az = 0.f, aw = 0.f;   // per-column partials
    float sq = 0.f;                                  // sum-of-squares partial

    if (n_rows == FAST_ROWS) {
        // One independent 4-load batch per thread: rows r0..r0+3, fixed c4.
        const int r0 = blockIdx.x * ROWS_PER_BLOCK + rs * 4;
        const size_t base = (size_t)r0 * D4 + c4;
        float4 v0 = A4[base + 0 * D4];
        float4 v1 = A4[base + 1 * D4];
        float4 v2 = A4[base + 2 * D4];
        float4 v3 = A4[base + 3 * D4];

        ax = ((v0.x + v1.x) + (v2.x + v3.x));
        ay = ((v0.y + v1.y) + (v2.y + v3.y));
        az = ((v0.z + v1.z) + (v2.z + v3.z));
        aw = ((v0.w + v1.w) + (v2.w + v3.w));

        sq = fmaf(v0.x, v0.x, sq); sq = fmaf(v0.y, v0.y, sq);
        sq = fmaf(v0.z, v0.z, sq); sq = fmaf(v0.w, v0.w, sq);
        sq = fmaf(v1.x, v1.x, sq); sq = fmaf(v1.y, v1.y, sq);
        sq = fmaf(v1.z, v1.z, sq); sq = fmaf(v1.w, v1.w, sq);
        sq = fmaf(v2.x, v2.x, sq); sq = fmaf(v2.y, v2.y, sq);
        sq = fmaf(v2.z, v2.z, sq); sq = fmaf(v2.w, v2.w, sq);
        sq = fmaf(v3.x, v3.x, sq); sq = fmaf(v3.y, v3.y, sq);
        sq = fmaf(v3.z, v3.z, sq); sq = fmaf(v3.w, v3.w, sq);
    } else {
        // Generic fallback (unused for this problem's fixed shape).
        for (int r0 = blockIdx.x * ROWS_PER_BLOCK; r0 < n_rows;
             r0 += GRID * ROWS_PER_BLOCK) {
            #pragma unroll
            for (int j = 0; j < 4; j++) {
                int row = r0 + rs * 4 + j;
                if (row < n_rows) {
                    float4 v = A4[(size_t)row * D4 + c4];
                    ax += v.x; ay += v.y; az += v.z; aw += v.w;
                    sq = fmaf(v.x, v.x, sq);
                    sq = fmaf(v.y, v.y, sq);
                    sq = fmaf(v.z, v.z, sq);
                    sq = fmaf(v.w, v.w, sq);
                }
            }
        }
    }

    // ---- combine the 4 row-phases for colsum via smem ----
    __shared__ float4 sc[4][D4];
    sc[rs][c4] = make_float4(ax, ay, az, aw);

    // ---- sumsq: warp shuffle reduce ----
    #pragma unroll
    for (int off = 16; off > 0; off >>= 1)
        sq += __shfl_xor_sync(0xFFFFFFFFu, sq, off);

    __shared__ float swarp[TPB / 32];
    if ((t & 31) == 0) swarp[t >> 5] = sq;
    __syncthreads();

    if (t < D4) {
        float4 s0 = sc[0][t];
        float4 s1 = sc[1][t];
        float4 s2 = sc[2][t];
        float4 s3 = sc[3][t];
        atomicAdd(&g_colsum[4 * t + 0], (s0.x + s1.x) + (s2.x + s3.x));
        atomicAdd(&g_colsum[4 * t + 1], (s0.y + s1.y) + (s2.y + s3.y));
        atomicAdd(&g_colsum[4 * t + 2], (s0.z + s1.z) + (s2.z + s3.z));
        atomicAdd(&g_colsum[4 * t + 3], (s0.w + s1.w) + (s2.w + s3.w));
    }
    if (t < TPB / 32) {
        float w = swarp[t];
        #pragma unroll
        for (int off = 8; off > 0; off >>= 1)
            w += __shfl_xor_sync(0xFFFFu, w, off);
        if (t == 0) atomicAdd(&g_sumsq, w);
    }

    // ---- last-block-finishes ----
    __syncthreads();
    __shared__ int is_last;
    if (t == 0) {
        __threadfence();
        unsigned prev = atomicAdd(&g_count, 1u);
        is_last = (prev == gridDim.x - 1u);
    }
    __syncthreads();

    if (is_last) {
        float v = g_colsum[t];       // TPB == D == 512
        float p = v * v;
        #pragma unroll
        for (int off = 16; off > 0; off >>= 1)
            p += __shfl_xor_sync(0xFFFFFFFFu, p, off);

        __shared__ float fwarp[TPB / 32];
        if ((t & 31) == 0) fwarp[t >> 5] = p;
        __syncthreads();

        if (t == 0) {
            float tot = 0.f;
            #pragma unroll
            for (int w = 0; w < TPB / 32; w++) tot += fwarp[w];
            double denom = (double)n_rows * (double)(n_rows - 1);
            out[0] = (float)(((double)tot - (double)g_sumsq) / denom);
            g_sumsq = 0.f;
            g_count = 0u;
        }
        g_colsum[t] = 0.f;           // reset for next graph replay
    }
}

extern "C" void kernel_launch(void* const* d_in, const int* in_sizes, int n_in,
                              void* d_out, int out_size) {
    const float* A = (const float*)d_in[0];
    const int n_rows = in_sizes[0] / D;   // 16384
    ddc2_fused_kernel<<<GRID, TPB>>>(A, n_rows, (float*)d_out);
}

// round 4
// speedup vs baseline: 3.7350x; 3.7350x over previous
#include <cuda_runtime.h>

// A is [16384, 512] fp32 row-major.
// out = (||colsum||^2 - sum(A*A)) / (n*(n-1))
#define D      512
#define D4     128                  // float4 chunks per row
#define GRID   256
#define TPB    512
#define ROWS_PER_BLOCK 64           // 16384 / 256
#define FAST_ROWS 16384

// Scratch (no allocs allowed). g_part/g_sqpart are fully overwritten every
// launch; only g_count needs reset (done by the last block).
__device__ float        g_part[GRID * D];   // per-block colsum partials
__device__ float        g_sqpart[GRID];     // per-block sumsq partials
__device__ unsigned int g_count;

__global__ void __launch_bounds__(TPB, 2)
ddc2_fused_kernel(const float* __restrict__ A, int n_rows, float* __restrict__ out) {
    const int t  = threadIdx.x;
    const int c4 = t & (D4 - 1);     // float4 column chunk owned by this thread
    const int rs = t >> 7;           // row phase 0..3 within the block

    const float4* __restrict__ A4 = reinterpret_cast<const float4*>(A);

    float ax = 0.f, ay = 0.f, az = 0.f, aw = 0.f;
    float sq = 0.f;

    if (n_rows == FAST_ROWS) {
        // Block owns 64 consecutive rows; phase rs owns 16 of them.
        // Two batches of 8 independent LDG.128 (MLP=8).
        const int r0 = blockIdx.x * ROWS_PER_BLOCK + rs * 16;
        const size_t base = (size_t)r0 * D4 + c4;
        #pragma unroll
        for (int half = 0; half < 2; half++) {
            float4 v[8];
            #pragma unroll
            for (int i = 0; i < 8; i++)
                v[i] = A4[base + (size_t)(half * 8 + i) * D4];
            #pragma unroll
            for (int i = 0; i < 8; i++) {
                ax += v[i].x; ay += v[i].y; az += v[i].z; aw += v[i].w;
                sq = fmaf(v[i].x, v[i].x, sq);
                sq = fmaf(v[i].y, v[i].y, sq);
                sq = fmaf(v[i].z, v[i].z, sq);
                sq = fmaf(v[i].w, v[i].w, sq);
            }
        }
    } else {
        // Generic fallback (unused for this fixed shape).
        for (int row = blockIdx.x * ROWS_PER_BLOCK + rs; row < n_rows;
             row += GRID * ROWS_PER_BLOCK) { /* degenerate-safe */
        }
        for (int row = blockIdx.x + rs * GRID; row < n_rows; row += 4 * GRID) {
            float4 v = A4[(size_t)row * D4 + c4];
            ax += v.x; ay += v.y; az += v.z; aw += v.w;
            sq = fmaf(v.x, v.x, sq); sq = fmaf(v.y, v.y, sq);
            sq = fmaf(v.z, v.z, sq); sq = fmaf(v.w, v.w, sq);
        }
    }

    // ---- combine the 4 row-phases via smem ----
    __shared__ float4 sc[4][D4];
    sc[rs][c4] = make_float4(ax, ay, az, aw);

    // ---- sumsq: warp shuffle reduce ----
    #pragma unroll
    for (int off = 16; off > 0; off >>= 1)
        sq += __shfl_xor_sync(0xFFFFFFFFu, sq, off);

    __shared__ float swarp[TPB / 32];
    if ((t & 31) == 0) swarp[t >> 5] = sq;
    __syncthreads();

    // ---- plain (non-atomic) partial writes: private row per block ----
    float4* __restrict__ P4 = reinterpret_cast<float4*>(g_part);
    if (t < D4) {
        float4 s0 = sc[0][t];
        float4 s1 = sc[1][t];
        float4 s2 = sc[2][t];
        float4 s3 = sc[3][t];
        float4 r;
        r.x = (s0.x + s1.x) + (s2.x + s3.x);
        r.y = (s0.y + s1.y) + (s2.y + s3.y);
        r.z = (s0.z + s1.z) + (s2.z + s3.z);
        r.w = (s0.w + s1.w) + (s2.w + s3.w);
        P4[blockIdx.x * D4 + t] = r;
    }
    if (t < TPB / 32) {
        float w = swarp[t];
        #pragma unroll
        for (int off = 8; off > 0; off >>= 1)
            w += __shfl_xor_sync(0xFFFFu, w, off);
        if (t == 0) g_sqpart[blockIdx.x] = w;
    }

    // ---- last-block-finishes (only atomic in the kernel: the counter) ----
    __syncthreads();
    __shared__ int is_last;
    if (t == 0) {
        __threadfence();             // publish this block's partial stores
        unsigned prev = atomicAdd(&g_count, 1u);
        is_last = (prev == gridDim.x - 1u);
    }
    __syncthreads();

    if (is_last) {
        // Reduce the 256x512 partial matrix (L2-resident) + 256 sq partials.
        // Thread (c4, rs) sums blocks b = rs + 4k, k = 0..63, MLP=8 unroll.
        float4 acc = make_float4(0.f, 0.f, 0.f, 0.f);
        #pragma unroll 8
        for (int k = 0; k < GRID / 4; k++) {
            float4 v = P4[(size_t)(rs + 4 * k) * D4 + c4];
            acc.x += v.x; acc.y += v.y; acc.z += v.z; acc.w += v.w;
        }
        sc[rs][c4] = acc;

        // sumsq partial pickup: threads 0..255 grab one each
        float q = (t < GRID) ? g_sqpart[t] : 0.f;

        __syncthreads();

        float p = 0.f;
        if (t < D4) {
            float4 s0 = sc[0][t];
            float4 s1 = sc[1][t];
            float4 s2 = sc[2][t];
            float4 s3 = sc[3][t];
            float cx = (s0.x + s1.x) + (s2.x + s3.x);
            float cy = (s0.y + s1.y) + (s2.y + s3.y);
            float cz = (s0.z + s1.z) + (s2.z + s3.z);
            float cw = (s0.w + s1.w) + (s2.w + s3.w);
            p = cx * cx + cy * cy + cz * cz + cw * cw;   // ||colsum||^2 partial
        }

        float r = p - q;   // accumulate (dot - sumsq) in one reduction
        #pragma unroll
        for (int off = 16; off > 0; off >>= 1)
            r += __shfl_xor_sync(0xFFFFFFFFu, r, off);

        __shared__ float fwarp[TPB / 32];
        if ((t & 31) == 0) fwarp[t >> 5] = r;
        __syncthreads();

        if (t == 0) {
            float tot = 0.f;
            #pragma unroll
            for (int w = 0; w < TPB / 32; w++) tot += fwarp[w];
            double denom = (double)n_rows * (double)(n_rows - 1);
            out[0] = (float)((double)tot / denom);
            g_count = 0u;            // reset for next graph replay
        }
    }
}

extern "C" void kernel_launch(void* const* d_in, const int* in_sizes, int n_in,
                              void* d_out, int out_size) {
    const float* A = (const float*)d_in[0];
    const int n_rows = in_sizes[0] / D;   // 16384
    ddc2_fused_kernel<<<GRID, TPB>>>(A, n_rows, (float*)d_out);
}